// round 4
// baseline (speedup 1.0000x reference)
#include <cuda_runtime.h>

#define MAX_BLOCKS 4096
#define CHUNK_IT   2                       // iterations per chunk
#define CHUNK_F4   (CHUNK_IT * 256)        // 512 float4 pairs per chunk (8KB/stream)

__device__ float        g_partials[MAX_BLOCKS];
__device__ unsigned int g_count = 0;       // completion counter (self-resetting)
__device__ unsigned int g_chunk = 0;       // work-stealing counter (self-resetting)

__global__ void __launch_bounds__(256) fused_dot_mean_ws_kernel(
    const float4* __restrict__ p4,
    const float4* __restrict__ c4,
    const float*  __restrict__ p,
    const float*  __restrict__ c,
    int n4, long long n, int nchunks,
    float* __restrict__ out, double inv_rows)
{
    const int tid  = threadIdx.x;
    const int lane = tid & 31;
    const int wid  = tid >> 5;

    __shared__ int s_chunk[2];

    float s = 0.0f;

    // Prime the pipeline: grab first chunk.
    if (tid == 0) s_chunk[0] = (int)atomicAdd(&g_chunk, 1u);
    __syncthreads();
    int c_id = s_chunk[0];
    int buf = 0;

    while (c_id < nchunks) {
        // Prefetch next chunk id (hides ATOMG latency behind this chunk's work).
        if (tid == 0) s_chunk[buf ^ 1] = (int)atomicAdd(&g_chunk, 1u);

        const int base = c_id * CHUNK_F4;
        if (base + CHUNK_F4 <= n4) {
            // Fast path: full chunk, no bounds checks.
            #pragma unroll
            for (int it = 0; it < CHUNK_IT; it++) {
                int i = base + it * 256 + tid;
                float4 a = __ldcs(&p4[i]);
                float4 b = __ldcs(&c4[i]);
                s += a.x * b.x;
                s += a.y * b.y;
                s += a.z * b.z;
                s += a.w * b.w;
            }
        } else {
            // Tail chunk: guarded.
            #pragma unroll
            for (int it = 0; it < CHUNK_IT; it++) {
                int i = base + it * 256 + tid;
                if (i < n4) {
                    float4 a = __ldcs(&p4[i]);
                    float4 b = __ldcs(&c4[i]);
                    s += a.x * b.x;
                    s += a.y * b.y;
                    s += a.z * b.z;
                    s += a.w * b.w;
                }
            }
        }

        __syncthreads();                    // next chunk id is ready
        buf ^= 1;
        c_id = s_chunk[buf];
    }

    // Warp reduction.
    #pragma unroll
    for (int o = 16; o > 0; o >>= 1)
        s += __shfl_xor_sync(0xffffffffu, s, o);

    __shared__ float wsum[8];
    if (lane == 0) wsum[wid] = s;
    __syncthreads();

    __shared__ bool is_last;
    if (tid == 0) {
        float bs = 0.0f;
        #pragma unroll
        for (int w = 0; w < 8; w++) bs += wsum[w];
        g_partials[blockIdx.x] = bs;
        __threadfence();
        unsigned int t = atomicAdd(&g_count, 1u);
        is_last = (t == gridDim.x - 1);
    }
    __syncthreads();

    if (is_last) {
        __threadfence();
        double d = 0.0;
        for (unsigned int k = tid; k < gridDim.x; k += blockDim.x)
            d += (double)g_partials[k];
        // Scalar tail beyond 4*n4 (absent for this shape; kept for safety).
        for (long long j = 4LL * n4 + tid; j < n; j += blockDim.x)
            d += (double)p[j] * (double)c[j];

        #pragma unroll
        for (int o = 16; o > 0; o >>= 1)
            d += __shfl_xor_sync(0xffffffffu, d, o);

        __shared__ double dsum[8];
        if (lane == 0) dsum[wid] = d;
        __syncthreads();
        if (tid == 0) {
            double tot = 0.0;
            #pragma unroll
            for (int w = 0; w < 8; w++) tot += dsum[w];
            *out = (float)(tot * inv_rows);
            g_count = 0;                    // reset for next graph replay
            g_chunk = 0;
        }
    }
}

extern "C" void kernel_launch(void* const* d_in, const int* in_sizes, int n_in,
                              void* d_out, int out_size) {
    const float* probs     = (const float*)d_in[0];
    const float* centroids = (const float*)d_in[1];
    float* out = (float*)d_out;

    const long long n    = (long long)in_sizes[0];   // 101,000,000
    const long long rows = n / 101;                  // K = 101
    const int  n4        = (int)(n >> 2);            // 25,250,000

    const int nchunks = (n4 + CHUNK_F4 - 1) / CHUNK_F4;

    const int threads = 256;
    int blocks = 148 * 8;                            // persistent: one resident wave
    if (blocks > nchunks) blocks = nchunks;
    if (blocks > MAX_BLOCKS) blocks = MAX_BLOCKS;
    if (blocks < 1) blocks = 1;

    fused_dot_mean_ws_kernel<<<blocks, threads>>>(
        (const float4*)probs, (const float4*)centroids,
        probs, centroids, n4, n, nchunks, out, 1.0 / (double)rows);
}

// round 5
// speedup vs baseline: 1.0818x; 1.0818x over previous
#include <cuda_runtime.h>

#define MAX_BLOCKS 4096
#define WCHUNK_IT  16                      // iterations per warp-chunk
#define WCHUNK_F4  (WCHUNK_IT * 32)        // 512 float4 pairs per warp-chunk

__device__ float        g_partials[MAX_BLOCKS];
__device__ unsigned int g_count = 0;       // completion counter (self-resetting)
__device__ unsigned int g_chunk = 0;       // work-stealing counter (self-resetting)

__global__ void __launch_bounds__(256) fused_dot_mean_wws_kernel(
    const float4* __restrict__ p4,
    const float4* __restrict__ c4,
    const float*  __restrict__ p,
    const float*  __restrict__ c,
    int n4, long long n, unsigned int nchunks,
    float* __restrict__ out, double inv_rows)
{
    const int tid  = threadIdx.x;
    const int lane = tid & 31;
    const int wid  = tid >> 5;

    float s = 0.0f;

    // Warp-level work stealing: no block barriers in the hot loop.
    unsigned int cur;
    if (lane == 0) cur = atomicAdd(&g_chunk, 1u);
    cur = __shfl_sync(0xffffffffu, cur, 0);

    while (cur < nchunks) {
        // Issue the steal for the NEXT chunk now; its ~318-cyc latency hides
        // under this chunk's ~8KB of loads. Result consumed by shfl at the end.
        unsigned int nxt;
        if (lane == 0) nxt = atomicAdd(&g_chunk, 1u);

        const int base = (int)cur * WCHUNK_F4 + lane;
        if ((int)cur * WCHUNK_F4 + WCHUNK_F4 <= n4) {
            // Full chunk: 16 unrolled iterations -> 32 independent LDG.128.
            #pragma unroll
            for (int it = 0; it < WCHUNK_IT; it++) {
                int i = base + it * 32;
                float4 a = __ldcs(&p4[i]);
                float4 b = __ldcs(&c4[i]);
                s += a.x * b.x;
                s += a.y * b.y;
                s += a.z * b.z;
                s += a.w * b.w;
            }
        } else {
            // Tail chunk: guarded.
            #pragma unroll
            for (int it = 0; it < WCHUNK_IT; it++) {
                int i = base + it * 32;
                if (i < n4) {
                    float4 a = __ldcs(&p4[i]);
                    float4 b = __ldcs(&c4[i]);
                    s += a.x * b.x;
                    s += a.y * b.y;
                    s += a.z * b.z;
                    s += a.w * b.w;
                }
            }
        }

        cur = __shfl_sync(0xffffffffu, nxt, 0);
    }

    // Warp reduction.
    #pragma unroll
    for (int o = 16; o > 0; o >>= 1)
        s += __shfl_xor_sync(0xffffffffu, s, o);

    __shared__ float wsum[8];
    if (lane == 0) wsum[wid] = s;
    __syncthreads();

    __shared__ bool is_last;
    if (tid == 0) {
        float bs = 0.0f;
        #pragma unroll
        for (int w = 0; w < 8; w++) bs += wsum[w];
        g_partials[blockIdx.x] = bs;
        __threadfence();
        unsigned int t = atomicAdd(&g_count, 1u);
        is_last = (t == gridDim.x - 1);
    }
    __syncthreads();

    if (is_last) {
        __threadfence();
        double d = 0.0;
        for (unsigned int k = tid; k < gridDim.x; k += blockDim.x)
            d += (double)g_partials[k];
        // Scalar tail beyond 4*n4 (absent for this shape; kept for safety).
        for (long long j = 4LL * n4 + tid; j < n; j += blockDim.x)
            d += (double)p[j] * (double)c[j];

        #pragma unroll
        for (int o = 16; o > 0; o >>= 1)
            d += __shfl_xor_sync(0xffffffffu, d, o);

        __shared__ double dsum[8];
        if (lane == 0) dsum[wid] = d;
        __syncthreads();
        if (tid == 0) {
            double tot = 0.0;
            #pragma unroll
            for (int w = 0; w < 8; w++) tot += dsum[w];
            *out = (float)(tot * inv_rows);
            g_count = 0;                    // reset for next graph replay
            g_chunk = 0;
        }
    }
}

extern "C" void kernel_launch(void* const* d_in, const int* in_sizes, int n_in,
                              void* d_out, int out_size) {
    const float* probs     = (const float*)d_in[0];
    const float* centroids = (const float*)d_in[1];
    float* out = (float*)d_out;

    const long long n    = (long long)in_sizes[0];   // 101,000,000
    const long long rows = n / 101;                  // K = 101
    const int  n4        = (int)(n >> 2);            // 25,250,000

    const unsigned int nchunks = (unsigned int)((n4 + WCHUNK_F4 - 1) / WCHUNK_F4);

    const int threads = 256;
    int blocks = 148 * 8;                            // persistent: one resident wave
    if (blocks > MAX_BLOCKS) blocks = MAX_BLOCKS;
    if (blocks < 1) blocks = 1;

    fused_dot_mean_wws_kernel<<<blocks, threads>>>(
        (const float4*)probs, (const float4*)centroids,
        probs, centroids, n4, n, nchunks, out, 1.0 / (double)rows);
}

// round 6
// speedup vs baseline: 1.5000x; 1.3866x over previous
#include <cuda_runtime.h>

#define MAX_BLOCKS 4096

__device__ float        g_partials[MAX_BLOCKS];
__device__ unsigned int g_count = 0;   // self-resetting: 0 before every run

// One full wave: 8 blocks/SM * 148 SMs, 256 threads, explicit MLP=8.
__global__ void __launch_bounds__(256) fused_dot_mean_kernel(
    const float4* __restrict__ p4,
    const float4* __restrict__ c4,
    const float*  __restrict__ p,
    const float*  __restrict__ c,
    int n4, long long n,
    float* __restrict__ out, double inv_rows)
{
    const int stride = gridDim.x * blockDim.x;
    const int tid0   = blockIdx.x * blockDim.x + threadIdx.x;

    float s0 = 0.0f, s1 = 0.0f, s2 = 0.0f, s3 = 0.0f;

    int i = tid0;
    // Main loop: 8 front-batched LDG.128 per iteration (explicit MLP).
    for (; i + 3 * stride < n4; i += 4 * stride) {
        // All 8 loads issued before any use -> 8 outstanding LDG.128.
        float4 a0 = __ldcs(&p4[i]);
        float4 a1 = __ldcs(&p4[i +     stride]);
        float4 a2 = __ldcs(&p4[i + 2 * stride]);
        float4 a3 = __ldcs(&p4[i + 3 * stride]);
        float4 b0 = __ldcs(&c4[i]);
        float4 b1 = __ldcs(&c4[i +     stride]);
        float4 b2 = __ldcs(&c4[i + 2 * stride]);
        float4 b3 = __ldcs(&c4[i + 3 * stride]);

        s0 += a0.x * b0.x; s0 += a0.y * b0.y; s0 += a0.z * b0.z; s0 += a0.w * b0.w;
        s1 += a1.x * b1.x; s1 += a1.y * b1.y; s1 += a1.z * b1.z; s1 += a1.w * b1.w;
        s2 += a2.x * b2.x; s2 += a2.y * b2.y; s2 += a2.z * b2.z; s2 += a2.w * b2.w;
        s3 += a3.x * b3.x; s3 += a3.y * b3.y; s3 += a3.z * b3.z; s3 += a3.w * b3.w;
    }
    // Remainder: single-step grid-stride.
    for (; i < n4; i += stride) {
        float4 a = __ldcs(&p4[i]);
        float4 b = __ldcs(&c4[i]);
        s0 += a.x * b.x; s0 += a.y * b.y; s0 += a.z * b.z; s0 += a.w * b.w;
    }
    float s = (s0 + s1) + (s2 + s3);

    // Scalar tail beyond 4*n4 (absent for this shape; kept for safety).
    for (long long j = 4LL * n4 + tid0; j < n; j += stride)
        s += p[j] * c[j];

    // Warp reduction.
    #pragma unroll
    for (int o = 16; o > 0; o >>= 1)
        s += __shfl_xor_sync(0xffffffffu, s, o);

    __shared__ float wsum[8];
    const int lane = threadIdx.x & 31;
    const int wid  = threadIdx.x >> 5;
    if (lane == 0) wsum[wid] = s;
    __syncthreads();

    __shared__ bool is_last;
    if (threadIdx.x == 0) {
        float bs = 0.0f;
        #pragma unroll
        for (int w = 0; w < 8; w++) bs += wsum[w];
        g_partials[blockIdx.x] = bs;
        __threadfence();
        unsigned int t = atomicAdd(&g_count, 1u);
        is_last = (t == gridDim.x - 1);
    }
    __syncthreads();

    if (is_last) {
        __threadfence();
        double d = 0.0;
        for (unsigned int k = threadIdx.x; k < gridDim.x; k += blockDim.x)
            d += (double)g_partials[k];
        #pragma unroll
        for (int o = 16; o > 0; o >>= 1)
            d += __shfl_xor_sync(0xffffffffu, d, o);

        __shared__ double dsum[8];
        if (lane == 0) dsum[wid] = d;
        __syncthreads();
        if (threadIdx.x == 0) {
            double tot = 0.0;
            #pragma unroll
            for (int w = 0; w < 8; w++) tot += dsum[w];
            *out = (float)(tot * inv_rows);
            g_count = 0;   // reset for next graph replay
        }
    }
}

extern "C" void kernel_launch(void* const* d_in, const int* in_sizes, int n_in,
                              void* d_out, int out_size) {
    const float* probs     = (const float*)d_in[0];
    const float* centroids = (const float*)d_in[1];
    float* out = (float*)d_out;

    const long long n    = (long long)in_sizes[0];   // 101,000,000
    const long long rows = n / 101;                  // K = 101
    const int  n4        = (int)(n >> 2);            // 25,250,000

    const int threads = 256;
    int blocks = 148 * 8;                            // exactly one full wave
    long long max_blocks = ((long long)n4 + threads - 1) / threads;
    if (blocks > max_blocks) blocks = (int)max_blocks;
    if (blocks > MAX_BLOCKS) blocks = MAX_BLOCKS;
    if (blocks < 1) blocks = 1;

    fused_dot_mean_kernel<<<blocks, threads>>>(
        (const float4*)probs, (const float4*)centroids,
        probs, centroids, n4, n, out, 1.0 / (double)rows);
}

// round 7
// speedup vs baseline: 1.5117x; 1.0078x over previous
#include <cuda_runtime.h>

#define MAX_BLOCKS 4096

__device__ float        g_partials[MAX_BLOCKS];
__device__ unsigned int g_count = 0;   // self-resetting: 0 before every run

// 128-bit read-only load with 256B L2 prefetch hint.
__device__ __forceinline__ float4 ld_stream(const float4* ptr) {
    float4 v;
    asm("ld.global.nc.L2::256B.v4.f32 {%0,%1,%2,%3}, [%4];"
        : "=f"(v.x), "=f"(v.y), "=f"(v.z), "=f"(v.w)
        : "l"(ptr));
    return v;
}

// One full wave: 8 blocks/SM * 148 SMs, 256 threads.
__global__ void __launch_bounds__(256) fused_dot_mean_kernel(
    const float4* __restrict__ p4,
    const float4* __restrict__ c4,
    const float*  __restrict__ p,
    const float*  __restrict__ c,
    int n4, long long n,
    float* __restrict__ out, double inv_rows)
{
    float s = 0.0f;
    const int stride = gridDim.x * blockDim.x;
    const int tid0   = blockIdx.x * blockDim.x + threadIdx.x;

    // Main vectorized loop (R3 structure — best measured).
    int i = tid0;
    #pragma unroll 8
    for (; i < n4; i += stride) {
        float4 a = ld_stream(&p4[i]);
        float4 b = ld_stream(&c4[i]);
        s += a.x * b.x;
        s += a.y * b.y;
        s += a.z * b.z;
        s += a.w * b.w;
    }

    // Scalar tail beyond 4*n4 (absent for this shape; kept for safety).
    for (long long j = 4LL * n4 + tid0; j < n; j += stride)
        s += p[j] * c[j];

    // Warp reduction.
    #pragma unroll
    for (int o = 16; o > 0; o >>= 1)
        s += __shfl_xor_sync(0xffffffffu, s, o);

    __shared__ float wsum[8];
    const int lane = threadIdx.x & 31;
    const int wid  = threadIdx.x >> 5;
    if (lane == 0) wsum[wid] = s;
    __syncthreads();

    __shared__ bool is_last;
    if (threadIdx.x == 0) {
        float bs = 0.0f;
        #pragma unroll
        for (int w = 0; w < 8; w++) bs += wsum[w];
        g_partials[blockIdx.x] = bs;
        __threadfence();
        unsigned int t = atomicAdd(&g_count, 1u);
        is_last = (t == gridDim.x - 1);
    }
    __syncthreads();

    if (is_last) {
        __threadfence();
        double d = 0.0;
        for (unsigned int k = threadIdx.x; k < gridDim.x; k += blockDim.x)
            d += (double)g_partials[k];
        #pragma unroll
        for (int o = 16; o > 0; o >>= 1)
            d += __shfl_xor_sync(0xffffffffu, d, o);

        __shared__ double dsum[8];
        if (lane == 0) dsum[wid] = d;
        __syncthreads();
        if (threadIdx.x == 0) {
            double tot = 0.0;
            #pragma unroll
            for (int w = 0; w < 8; w++) tot += dsum[w];
            *out = (float)(tot * inv_rows);
            g_count = 0;   // reset for next graph replay
        }
    }
}

extern "C" void kernel_launch(void* const* d_in, const int* in_sizes, int n_in,
                              void* d_out, int out_size) {
    const float* probs     = (const float*)d_in[0];
    const float* centroids = (const float*)d_in[1];
    float* out = (float*)d_out;

    const long long n    = (long long)in_sizes[0];   // 101,000,000
    const long long rows = n / 101;                  // K = 101
    const int  n4        = (int)(n >> 2);            // 25,250,000

    const int threads = 256;
    int blocks = 148 * 8;                            // exactly one full wave
    long long max_blocks = ((long long)n4 + threads - 1) / threads;
    if (blocks > max_blocks) blocks = (int)max_blocks;
    if (blocks > MAX_BLOCKS) blocks = MAX_BLOCKS;
    if (blocks < 1) blocks = 1;

    fused_dot_mean_kernel<<<blocks, threads>>>(
        (const float4*)probs, (const float4*)centroids,
        probs, centroids, n4, n, out, 1.0 / (double)rows);
}